// round 10
// baseline (speedup 1.0000x reference)
#include <cuda_runtime.h>

// genMaskPatchNew: softmax(C=2) -> 32x32 avgpool stride2 -> per-class top-1
// window -> rect coords (oxy [B,2,2,2]) + union mask [B,1,256,256].
// Class1 pooled = (1024 - S0)/1024  =>  argmax(class1) == argmin(S0).
//
// One block per image (128 blocks, single wave). 512 threads.
// Phase 1: all 8 float4 loads per row-pair hoisted (MLP ~64KB/SM in flight),
//          horizontal 32-wide window sums via warp prefix-scan, accumulated
//          into row-pair sums ps2[128][113] in smem.
// Phase 2: window sum = 16 smem adds; block arg-max/arg-min, first-index
//          tie-break matching jnp.argmax.
// Phase 3: oxy (float, or raw int32 when oxy is the sole output) + mask
//          (float4 stores).

#define BATCH 128
#define HH 256
#define WW 256
#define PS 113            // (256-32)/2 + 1
#define NWIN (PS * PS)    // 12769
#define NTHREADS 512
#define NWARPS (NTHREADS / 32)

struct Sm {
    float ps2[128][PS];        // pair-of-rows horizontal window sums
    float rowpref[NWARPS][264];// per-warp prefix staging (257 used, padded)
    float redMaxV[NTHREADS];
    float redMinV[NTHREADS];
    int   redMaxI[NTHREADS];
    int   redMinI[NTHREADS];
    int   coords[8];
};

// Stabilized 2-class softmax prob of class 0, mirroring jax.nn.softmax's
// exp(x - max)/sum branch structure (accurate expf, single division).
__device__ __forceinline__ float prob0(float a /*x0*/, float c /*x1*/) {
    float d = c - a;
    if (d <= 0.f) {
        return 1.f / (1.f + expf(d));
    } else {
        float t = expf(-d);
        return t / (1.f + t);
    }
}

__global__ void __launch_bounds__(NTHREADS, 1)
genmask_kernel(const float* __restrict__ infeat, float* __restrict__ out,
               int oxyBase, int maskBase, int oxyAsInt)
{
    extern __shared__ char smraw[];
    Sm* sm = reinterpret_cast<Sm*>(smraw);

    const int b    = blockIdx.x;
    const int tid  = threadIdx.x;
    const int warp = tid >> 5;
    const int lane = tid & 31;

    const float* x0 = infeat + ((size_t)b * 2 + 0) * (HH * WW);
    const float* x1 = infeat + ((size_t)b * 2 + 1) * (HH * WW);

    // ---------------- Phase 1: horizontal window sums, paired rows ----------
    float* pr = &sm->rowpref[warp][0];

    for (int j = warp; j < 128; j += NWARPS) {       // j = row-pair index
        const int y0 = 2 * j, y1 = 2 * j + 1;
        // Hoist ALL loads for this iteration: 8 x LDG.128 per lane in flight.
        const float4* r00 = reinterpret_cast<const float4*>(x0 + y0 * WW);
        const float4* r01 = reinterpret_cast<const float4*>(x0 + y1 * WW);
        const float4* r10 = reinterpret_cast<const float4*>(x1 + y0 * WW);
        const float4* r11 = reinterpret_cast<const float4*>(x1 + y1 * WW);
        float4 A[2][2], C[2][2];                     // [sub][half]
        A[0][0] = r00[2 * lane];  A[0][1] = r00[2 * lane + 1];
        A[1][0] = r01[2 * lane];  A[1][1] = r01[2 * lane + 1];
        C[0][0] = r10[2 * lane];  C[0][1] = r10[2 * lane + 1];
        C[1][0] = r11[2 * lane];  C[1][1] = r11[2 * lane + 1];

        float acc0 = 0.f, acc1 = 0.f, acc2 = 0.f, acc3 = 0.f;
        #pragma unroll
        for (int sub = 0; sub < 2; ++sub) {
            float p[8];
            p[0] = prob0(A[sub][0].x, C[sub][0].x);
            p[1] = prob0(A[sub][0].y, C[sub][0].y);
            p[2] = prob0(A[sub][0].z, C[sub][0].z);
            p[3] = prob0(A[sub][0].w, C[sub][0].w);
            p[4] = prob0(A[sub][1].x, C[sub][1].x);
            p[5] = prob0(A[sub][1].y, C[sub][1].y);
            p[6] = prob0(A[sub][1].z, C[sub][1].z);
            p[7] = prob0(A[sub][1].w, C[sub][1].w);

            float incl[8];
            float run = 0.f;
            #pragma unroll
            for (int t = 0; t < 8; ++t) { run += p[t]; incl[t] = run; }

            // warp inclusive scan of per-lane totals
            float s = run;
            #pragma unroll
            for (int d = 1; d < 32; d <<= 1) {
                float v = __shfl_up_sync(0xffffffffu, s, d);
                if (lane >= d) s += v;
            }
            const float off = s - run;   // exclusive prefix for this lane

            if (lane == 0) pr[0] = 0.f;
            #pragma unroll
            for (int t = 0; t < 8; ++t) pr[8 * lane + t + 1] = off + incl[t];
            __syncwarp();

            // horizontal window sums: hsum[gx] = pr[2gx+32] - pr[2gx]
            {
                int gx = lane;
                float h0 = pr[2 * gx + 32] - pr[2 * gx];
                gx = lane + 32;
                float h1 = pr[2 * gx + 32] - pr[2 * gx];
                gx = lane + 64;
                float h2 = pr[2 * gx + 32] - pr[2 * gx];
                gx = lane + 96;
                float h3 = (gx < PS) ? (pr[2 * gx + 32] - pr[2 * gx]) : 0.f;
                acc0 += h0; acc1 += h1; acc2 += h2; acc3 += h3;
            }
            __syncwarp();
        }
        sm->ps2[j][lane]      = acc0;
        sm->ps2[j][lane + 32] = acc1;
        sm->ps2[j][lane + 64] = acc2;
        if (lane + 96 < PS) sm->ps2[j][lane + 96] = acc3;
    }
    __syncthreads();

    // ---------------- Phase 2: vertical sums + arg reduce -------------------
    float bestMaxV = -3.402823e38f; int bestMaxI = 0;
    float bestMinV =  3.402823e38f; int bestMinI = 0;

    for (int idx = tid; idx < NWIN; idx += NTHREADS) {
        const int gy = idx / PS;
        const int gx = idx - gy * PS;
        float s = 0.f;
        #pragma unroll
        for (int dj = 0; dj < 16; ++dj) s += sm->ps2[gy + dj][gx];
        if (s > bestMaxV) { bestMaxV = s; bestMaxI = idx; }   // strict: keeps first idx
        if (s < bestMinV) { bestMinV = s; bestMinI = idx; }
    }

    sm->redMaxV[tid] = bestMaxV; sm->redMaxI[tid] = bestMaxI;
    sm->redMinV[tid] = bestMinV; sm->redMinI[tid] = bestMinI;
    __syncthreads();

    for (int st = NTHREADS / 2; st > 0; st >>= 1) {
        if (tid < st) {
            float v = sm->redMaxV[tid + st]; int i2 = sm->redMaxI[tid + st];
            if (v > sm->redMaxV[tid] ||
                (v == sm->redMaxV[tid] && i2 < sm->redMaxI[tid])) {
                sm->redMaxV[tid] = v; sm->redMaxI[tid] = i2;
            }
            float w = sm->redMinV[tid + st]; int j2 = sm->redMinI[tid + st];
            if (w < sm->redMinV[tid] ||
                (w == sm->redMinV[tid] && j2 < sm->redMinI[tid])) {
                sm->redMinV[tid] = w; sm->redMinI[tid] = j2;
            }
        }
        __syncthreads();
    }

    if (tid == 0) {
        const int imax = sm->redMaxI[0];   // class 0 top-1
        const int imin = sm->redMinI[0];   // class 1 top-1 (= argmin of S0)
        const int py0 = imax / PS, px0 = imax - py0 * PS;
        const int py1 = imin / PS, px1 = imin - py1 * PS;

        int c[8];
        c[0] = px0 * 2;                       // ox0 class0
        c[1] = min(WW - 1, px0 * 2 + 31);     // ox1
        c[2] = py0 * 2;                       // oy0
        c[3] = min(HH - 1, py0 * 2 + 31);     // oy1
        c[4] = px1 * 2;
        c[5] = min(WW - 1, px1 * 2 + 31);
        c[6] = py1 * 2;
        c[7] = min(HH - 1, py1 * 2 + 31);
        #pragma unroll
        for (int i = 0; i < 8; ++i) sm->coords[i] = c[i];

        if (oxyBase >= 0) {
            // oxy layout [B, 2, 2, 2]: [c][0] = {ox0, ox1}, [c][1] = {oy0, oy1}
            if (oxyAsInt) {
                int* o = reinterpret_cast<int*>(out) + oxyBase + (size_t)b * 8;
                #pragma unroll
                for (int i = 0; i < 8; ++i) o[i] = c[i];
            } else {
                float* o = out + oxyBase + (size_t)b * 8;
                #pragma unroll
                for (int i = 0; i < 8; ++i) o[i] = (float)c[i];
            }
        }
    }
    __syncthreads();

    // ---------------- Phase 3: mask write -----------------------------------
    if (maskBase >= 0) {
        const int ox0a = sm->coords[0], ox1a = sm->coords[1];
        const int oy0a = sm->coords[2], oy1a = sm->coords[3];
        const int ox0b = sm->coords[4], ox1b = sm->coords[5];
        const int oy0b = sm->coords[6], oy1b = sm->coords[7];

        float4* mout = reinterpret_cast<float4*>(out + maskBase + (size_t)b * HH * WW);
        #pragma unroll 4
        for (int p4 = tid; p4 < (HH * WW) / 4; p4 += NTHREADS) {
            const int y = p4 >> 6;           // 64 float4 per row
            const int x = (p4 & 63) << 2;
            const bool ya = (y >= oy0a) & (y <= oy1a);
            const bool yb = (y >= oy0b) & (y <= oy1b);
            float4 v;
            int xx;
            xx = x;     v.x = ((ya & (xx >= ox0a) & (xx <= ox1a)) |
                               (yb & (xx >= ox0b) & (xx <= ox1b))) ? 1.f : 0.f;
            xx = x + 1; v.y = ((ya & (xx >= ox0a) & (xx <= ox1a)) |
                               (yb & (xx >= ox0b) & (xx <= ox1b))) ? 1.f : 0.f;
            xx = x + 2; v.z = ((ya & (xx >= ox0a) & (xx <= ox1a)) |
                               (yb & (xx >= ox0b) & (xx <= ox1b))) ? 1.f : 0.f;
            xx = x + 3; v.w = ((ya & (xx >= ox0a) & (xx <= ox1a)) |
                               (yb & (xx >= ox0b) & (xx <= ox1b))) ? 1.f : 0.f;
            mout[p4] = v;
        }
    }
}

extern "C" void kernel_launch(void* const* d_in, const int* in_sizes, int n_in,
                              void* d_out, int out_size)
{
    const float* infeat = (const float*)d_in[0];   // [128, 2, 256, 256] f32
    // d_in[1] labelTpesudo, d_in[2] labelT, d_in[3] FeatureDA, d_in[4] k: unused

    const long long oxyN  = (long long)BATCH * 8;
    const long long maskN = (long long)BATCH * HH * WW;

    int oxyBase = -1, maskBase = -1, oxyAsInt = 0;
    const long long os = (long long)out_size;
    if (os == oxyN + maskN)      { oxyBase = 0; maskBase = (int)oxyN; }
    else if (os == maskN)        { maskBase = 0; }
    else if (os == oxyN)         { oxyBase = 0; oxyAsInt = 1; }  // sole output: int32
    else                         { oxyBase = 0; maskBase = (int)oxyN; }

    cudaFuncSetAttribute(genmask_kernel,
                         cudaFuncAttributeMaxDynamicSharedMemorySize,
                         (int)sizeof(Sm));
    genmask_kernel<<<BATCH, NTHREADS, sizeof(Sm)>>>(infeat, (float*)d_out,
                                                    oxyBase, maskBase, oxyAsInt);
}

// round 11
// speedup vs baseline: 1.6394x; 1.6394x over previous
#include <cuda_runtime.h>

// genMaskPatchNew: softmax(C=2) -> 32x32 avgpool stride2 -> per-class top-1
// window -> rect coords (oxy [B,2,2,2]) + union mask [B,1,256,256].
// Class1 pooled = (1024 - S0)/1024  =>  argmax(class1) == argmin(S0).
//
// One block per image (128 blocks, single wave). 1024 threads (R10: was 512;
// occ 25%->50% and fast __expf sigmoid — measured issue-bound, not HBM-bound).
// Phase 1: all 8 float4 loads per row-pair hoisted, horizontal 32-wide window
//          sums via warp prefix-scan into ps2[128][113] in smem.
// Phase 2: window sum = 16 smem adds; block arg-max/arg-min, first-index
//          tie-break matching jnp.argmax.
// Phase 3: oxy (float, or raw int32 when oxy is the sole output) + mask.

#define BATCH 128
#define HH 256
#define WW 256
#define PS 113            // (256-32)/2 + 1
#define NWIN (PS * PS)    // 12769
#define NTHREADS 1024
#define NWARPS (NTHREADS / 32)

struct Sm {
    float ps2[128][PS];        // pair-of-rows horizontal window sums
    float rowpref[NWARPS][264];// per-warp prefix staging (257 used, padded)
    float redMaxV[NTHREADS];
    float redMinV[NTHREADS];
    int   redMaxI[NTHREADS];
    int   redMinI[NTHREADS];
    int   coords[8];
};

// Fast 2-class softmax prob of class 0. __expf rel-err ~2^-22 perturbs the
// 1024-elem window sums by ~1e-6 abs — far below measured top-1 gaps
// (R10 bench: exact-argmax rel_err = 0.0 with margin). Branchless, safe at
// extremes: d->+inf => exp=inf => p=0; d->-inf => exp=0 => p=1.
__device__ __forceinline__ float prob0(float a /*x0*/, float c /*x1*/) {
    return __fdividef(1.f, 1.f + __expf(c - a));
}

__global__ void __launch_bounds__(NTHREADS, 1)
genmask_kernel(const float* __restrict__ infeat, float* __restrict__ out,
               int oxyBase, int maskBase, int oxyAsInt)
{
    extern __shared__ char smraw[];
    Sm* sm = reinterpret_cast<Sm*>(smraw);

    const int b    = blockIdx.x;
    const int tid  = threadIdx.x;
    const int warp = tid >> 5;
    const int lane = tid & 31;

    const float* x0 = infeat + ((size_t)b * 2 + 0) * (HH * WW);
    const float* x1 = infeat + ((size_t)b * 2 + 1) * (HH * WW);

    // ---------------- Phase 1: horizontal window sums, paired rows ----------
    float* pr = &sm->rowpref[warp][0];

    for (int j = warp; j < 128; j += NWARPS) {       // j = row-pair index
        const int y0 = 2 * j, y1 = 2 * j + 1;
        // Hoist ALL loads for this iteration: 8 x LDG.128 per lane in flight.
        const float4* r00 = reinterpret_cast<const float4*>(x0 + y0 * WW);
        const float4* r01 = reinterpret_cast<const float4*>(x0 + y1 * WW);
        const float4* r10 = reinterpret_cast<const float4*>(x1 + y0 * WW);
        const float4* r11 = reinterpret_cast<const float4*>(x1 + y1 * WW);
        float4 A[2][2], C[2][2];                     // [sub][half]
        A[0][0] = r00[2 * lane];  A[0][1] = r00[2 * lane + 1];
        A[1][0] = r01[2 * lane];  A[1][1] = r01[2 * lane + 1];
        C[0][0] = r10[2 * lane];  C[0][1] = r10[2 * lane + 1];
        C[1][0] = r11[2 * lane];  C[1][1] = r11[2 * lane + 1];

        float acc0 = 0.f, acc1 = 0.f, acc2 = 0.f, acc3 = 0.f;
        #pragma unroll
        for (int sub = 0; sub < 2; ++sub) {
            float p[8];
            p[0] = prob0(A[sub][0].x, C[sub][0].x);
            p[1] = prob0(A[sub][0].y, C[sub][0].y);
            p[2] = prob0(A[sub][0].z, C[sub][0].z);
            p[3] = prob0(A[sub][0].w, C[sub][0].w);
            p[4] = prob0(A[sub][1].x, C[sub][1].x);
            p[5] = prob0(A[sub][1].y, C[sub][1].y);
            p[6] = prob0(A[sub][1].z, C[sub][1].z);
            p[7] = prob0(A[sub][1].w, C[sub][1].w);

            float incl[8];
            float run = 0.f;
            #pragma unroll
            for (int t = 0; t < 8; ++t) { run += p[t]; incl[t] = run; }

            // warp inclusive scan of per-lane totals
            float s = run;
            #pragma unroll
            for (int d = 1; d < 32; d <<= 1) {
                float v = __shfl_up_sync(0xffffffffu, s, d);
                if (lane >= d) s += v;
            }
            const float off = s - run;   // exclusive prefix for this lane

            if (lane == 0) pr[0] = 0.f;
            #pragma unroll
            for (int t = 0; t < 8; ++t) pr[8 * lane + t + 1] = off + incl[t];
            __syncwarp();

            // horizontal window sums: hsum[gx] = pr[2gx+32] - pr[2gx]
            {
                int gx = lane;
                float h0 = pr[2 * gx + 32] - pr[2 * gx];
                gx = lane + 32;
                float h1 = pr[2 * gx + 32] - pr[2 * gx];
                gx = lane + 64;
                float h2 = pr[2 * gx + 32] - pr[2 * gx];
                gx = lane + 96;
                float h3 = (gx < PS) ? (pr[2 * gx + 32] - pr[2 * gx]) : 0.f;
                acc0 += h0; acc1 += h1; acc2 += h2; acc3 += h3;
            }
            __syncwarp();
        }
        sm->ps2[j][lane]      = acc0;
        sm->ps2[j][lane + 32] = acc1;
        sm->ps2[j][lane + 64] = acc2;
        if (lane + 96 < PS) sm->ps2[j][lane + 96] = acc3;
    }
    __syncthreads();

    // ---------------- Phase 2: vertical sums + arg reduce -------------------
    float bestMaxV = -3.402823e38f; int bestMaxI = 0;
    float bestMinV =  3.402823e38f; int bestMinI = 0;

    for (int idx = tid; idx < NWIN; idx += NTHREADS) {
        const int gy = idx / PS;
        const int gx = idx - gy * PS;
        float s = 0.f;
        #pragma unroll
        for (int dj = 0; dj < 16; ++dj) s += sm->ps2[gy + dj][gx];
        if (s > bestMaxV) { bestMaxV = s; bestMaxI = idx; }   // strict: keeps first idx
        if (s < bestMinV) { bestMinV = s; bestMinI = idx; }
    }

    sm->redMaxV[tid] = bestMaxV; sm->redMaxI[tid] = bestMaxI;
    sm->redMinV[tid] = bestMinV; sm->redMinI[tid] = bestMinI;
    __syncthreads();

    for (int st = NTHREADS / 2; st > 0; st >>= 1) {
        if (tid < st) {
            float v = sm->redMaxV[tid + st]; int i2 = sm->redMaxI[tid + st];
            if (v > sm->redMaxV[tid] ||
                (v == sm->redMaxV[tid] && i2 < sm->redMaxI[tid])) {
                sm->redMaxV[tid] = v; sm->redMaxI[tid] = i2;
            }
            float w = sm->redMinV[tid + st]; int j2 = sm->redMinI[tid + st];
            if (w < sm->redMinV[tid] ||
                (w == sm->redMinV[tid] && j2 < sm->redMinI[tid])) {
                sm->redMinV[tid] = w; sm->redMinI[tid] = j2;
            }
        }
        __syncthreads();
    }

    if (tid == 0) {
        const int imax = sm->redMaxI[0];   // class 0 top-1
        const int imin = sm->redMinI[0];   // class 1 top-1 (= argmin of S0)
        const int py0 = imax / PS, px0 = imax - py0 * PS;
        const int py1 = imin / PS, px1 = imin - py1 * PS;

        int c[8];
        c[0] = px0 * 2;                       // ox0 class0
        c[1] = min(WW - 1, px0 * 2 + 31);     // ox1
        c[2] = py0 * 2;                       // oy0
        c[3] = min(HH - 1, py0 * 2 + 31);     // oy1
        c[4] = px1 * 2;
        c[5] = min(WW - 1, px1 * 2 + 31);
        c[6] = py1 * 2;
        c[7] = min(HH - 1, py1 * 2 + 31);
        #pragma unroll
        for (int i = 0; i < 8; ++i) sm->coords[i] = c[i];

        if (oxyBase >= 0) {
            // oxy layout [B, 2, 2, 2]: [c][0] = {ox0, ox1}, [c][1] = {oy0, oy1}
            if (oxyAsInt) {
                int* o = reinterpret_cast<int*>(out) + oxyBase + (size_t)b * 8;
                #pragma unroll
                for (int i = 0; i < 8; ++i) o[i] = c[i];
            } else {
                float* o = out + oxyBase + (size_t)b * 8;
                #pragma unroll
                for (int i = 0; i < 8; ++i) o[i] = (float)c[i];
            }
        }
    }
    __syncthreads();

    // ---------------- Phase 3: mask write -----------------------------------
    if (maskBase >= 0) {
        const int ox0a = sm->coords[0], ox1a = sm->coords[1];
        const int oy0a = sm->coords[2], oy1a = sm->coords[3];
        const int ox0b = sm->coords[4], ox1b = sm->coords[5];
        const int oy0b = sm->coords[6], oy1b = sm->coords[7];

        float4* mout = reinterpret_cast<float4*>(out + maskBase + (size_t)b * HH * WW);
        #pragma unroll 4
        for (int p4 = tid; p4 < (HH * WW) / 4; p4 += NTHREADS) {
            const int y = p4 >> 6;           // 64 float4 per row
            const int x = (p4 & 63) << 2;
            const bool ya = (y >= oy0a) & (y <= oy1a);
            const bool yb = (y >= oy0b) & (y <= oy1b);
            float4 v;
            int xx;
            xx = x;     v.x = ((ya & (xx >= ox0a) & (xx <= ox1a)) |
                               (yb & (xx >= ox0b) & (xx <= ox1b))) ? 1.f : 0.f;
            xx = x + 1; v.y = ((ya & (xx >= ox0a) & (xx <= ox1a)) |
                               (yb & (xx >= ox0b) & (xx <= ox1b))) ? 1.f : 0.f;
            xx = x + 2; v.z = ((ya & (xx >= ox0a) & (xx <= ox1a)) |
                               (yb & (xx >= ox0b) & (xx <= ox1b))) ? 1.f : 0.f;
            xx = x + 3; v.w = ((ya & (xx >= ox0a) & (xx <= ox1a)) |
                               (yb & (xx >= ox0b) & (xx <= ox1b))) ? 1.f : 0.f;
            mout[p4] = v;
        }
    }
}

extern "C" void kernel_launch(void* const* d_in, const int* in_sizes, int n_in,
                              void* d_out, int out_size)
{
    const float* infeat = (const float*)d_in[0];   // [128, 2, 256, 256] f32
    // d_in[1] labelTpesudo, d_in[2] labelT, d_in[3] FeatureDA, d_in[4] k: unused

    const long long oxyN  = (long long)BATCH * 8;
    const long long maskN = (long long)BATCH * HH * WW;

    int oxyBase = -1, maskBase = -1, oxyAsInt = 0;
    const long long os = (long long)out_size;
    if (os == oxyN + maskN)      { oxyBase = 0; maskBase = (int)oxyN; }
    else if (os == maskN)        { maskBase = 0; }
    else if (os == oxyN)         { oxyBase = 0; oxyAsInt = 1; }  // sole output: int32
    else                         { oxyBase = 0; maskBase = (int)oxyN; }

    cudaFuncSetAttribute(genmask_kernel,
                         cudaFuncAttributeMaxDynamicSharedMemorySize,
                         (int)sizeof(Sm));
    genmask_kernel<<<BATCH, NTHREADS, sizeof(Sm)>>>(infeat, (float*)d_out,
                                                    oxyBase, maskBase, oxyAsInt);
}

// round 12
// speedup vs baseline: 1.9791x; 1.2072x over previous
#include <cuda_runtime.h>

// genMaskPatchNew: softmax(C=2) -> 32x32 avgpool stride2 -> per-class top-1
// window -> rect coords (oxy [B,2,2,2]) + union mask [B,1,256,256].
// Class1 pooled = (1024 - S0)/1024  =>  argmax(class1) == argmin(S0).
//
// One block per image (128 blocks, single wave). 1024 threads.
// R11 ncu: L1(smem)=47% dominant -> R12: even-only prefix store (conflict-free
// window reads, 4-way STS instead of 8-way) + phase-2 per-column sliding
// window (16 adds -> 1 add+1 sub per step).

#define BATCH 128
#define HH 256
#define WW 256
#define PS 113            // (256-32)/2 + 1
#define NWIN (PS * PS)    // 12769
#define NTHREADS 1024
#define NWARPS (NTHREADS / 32)

struct Sm {
    float ps2[128][PS];        // pair-of-rows horizontal window sums
    float prX[NWARPS][132];    // per-warp even-position exclusive prefixes (129 used)
    float redMaxV[NTHREADS];
    float redMinV[NTHREADS];
    int   redMaxI[NTHREADS];
    int   redMinI[NTHREADS];
    int   coords[8];
};

// Fast 2-class softmax prob of class 0. __expf rel-err ~2^-22 perturbs the
// 1024-elem window sums by ~1e-6 abs — far below measured top-1 gaps
// (R10/R11: exact-argmax rel_err = 0.0). Branchless, safe at extremes.
__device__ __forceinline__ float prob0(float a /*x0*/, float c /*x1*/) {
    return __fdividef(1.f, 1.f + __expf(c - a));
}

__global__ void __launch_bounds__(NTHREADS, 1)
genmask_kernel(const float* __restrict__ infeat, float* __restrict__ out,
               int oxyBase, int maskBase, int oxyAsInt)
{
    extern __shared__ char smraw[];
    Sm* sm = reinterpret_cast<Sm*>(smraw);

    const int b    = blockIdx.x;
    const int tid  = threadIdx.x;
    const int warp = tid >> 5;
    const int lane = tid & 31;

    const float* x0 = infeat + ((size_t)b * 2 + 0) * (HH * WW);
    const float* x1 = infeat + ((size_t)b * 2 + 1) * (HH * WW);

    // ---------------- Phase 1: horizontal window sums, paired rows ----------
    float* pr = &sm->prX[warp][0];

    for (int j = warp; j < 128; j += NWARPS) {       // j = row-pair index
        const int y0 = 2 * j, y1 = 2 * j + 1;
        // Hoist ALL loads for this iteration: 8 x LDG.128 per lane in flight.
        const float4* r00 = reinterpret_cast<const float4*>(x0 + y0 * WW);
        const float4* r01 = reinterpret_cast<const float4*>(x0 + y1 * WW);
        const float4* r10 = reinterpret_cast<const float4*>(x1 + y0 * WW);
        const float4* r11 = reinterpret_cast<const float4*>(x1 + y1 * WW);
        float4 A[2][2], C[2][2];                     // [sub][half]
        A[0][0] = r00[2 * lane];  A[0][1] = r00[2 * lane + 1];
        A[1][0] = r01[2 * lane];  A[1][1] = r01[2 * lane + 1];
        C[0][0] = r10[2 * lane];  C[0][1] = r10[2 * lane + 1];
        C[1][0] = r11[2 * lane];  C[1][1] = r11[2 * lane + 1];

        float acc0 = 0.f, acc1 = 0.f, acc2 = 0.f, acc3 = 0.f;
        #pragma unroll
        for (int sub = 0; sub < 2; ++sub) {
            float p[8];
            p[0] = prob0(A[sub][0].x, C[sub][0].x);
            p[1] = prob0(A[sub][0].y, C[sub][0].y);
            p[2] = prob0(A[sub][0].z, C[sub][0].z);
            p[3] = prob0(A[sub][0].w, C[sub][0].w);
            p[4] = prob0(A[sub][1].x, C[sub][1].x);
            p[5] = prob0(A[sub][1].y, C[sub][1].y);
            p[6] = prob0(A[sub][1].z, C[sub][1].z);
            p[7] = prob0(A[sub][1].w, C[sub][1].w);

            float incl[8];
            float run = 0.f;
            #pragma unroll
            for (int t = 0; t < 8; ++t) { run += p[t]; incl[t] = run; }

            // warp inclusive scan of per-lane totals
            float s = run;
            #pragma unroll
            for (int d = 1; d < 32; d <<= 1) {
                float v = __shfl_up_sync(0xffffffffu, s, d);
                if (lane >= d) s += v;
            }
            const float off = s - run;   // exclusive prefix for this lane

            // Even-position exclusive prefixes only: prX[m] = E[2m].
            // E[8l+t+1] = off_l + incl[t]; even => t in {1,3,5,7} => m = 4l+1..4l+4.
            if (lane == 0) pr[0] = 0.f;
            pr[4 * lane + 1] = off + incl[1];
            pr[4 * lane + 2] = off + incl[3];
            pr[4 * lane + 3] = off + incl[5];
            pr[4 * lane + 4] = off + incl[7];
            __syncwarp();

            // hsum[gx] = E[2gx+32] - E[2gx] = prX[gx+16] - prX[gx]  (conflict-free)
            {
                float h0 = pr[lane + 16] - pr[lane];
                float h1 = pr[lane + 48] - pr[lane + 32];
                float h2 = pr[lane + 80] - pr[lane + 64];
                float h3 = (lane + 96 < PS) ? (pr[lane + 112] - pr[lane + 96]) : 0.f;
                acc0 += h0; acc1 += h1; acc2 += h2; acc3 += h3;
            }
            __syncwarp();
        }
        sm->ps2[j][lane]      = acc0;
        sm->ps2[j][lane + 32] = acc1;
        sm->ps2[j][lane + 64] = acc2;
        if (lane + 96 < PS) sm->ps2[j][lane + 96] = acc3;
    }
    __syncthreads();

    // ---------------- Phase 2: per-column sliding vertical sums -------------
    // 113 columns x 9 gy-segments of 13 -> threads 0..1016 active.
    float bestMaxV = -3.402823e38f; int bestMaxI = 0;
    float bestMinV =  3.402823e38f; int bestMinI = 0;

    if (tid < 113 * 9) {
        const int gx  = tid / 9;
        const int seg = tid - gx * 9;
        const int gy0 = seg * 13;
        const int gyE = (gy0 + 13 < PS) ? (gy0 + 13) : PS;

        float s = 0.f;
        #pragma unroll
        for (int dj = 0; dj < 16; ++dj) s += sm->ps2[gy0 + dj][gx];

        for (int gy = gy0; gy < gyE; ++gy) {
            const int idx = gy * PS + gx;
            if (s > bestMaxV) { bestMaxV = s; bestMaxI = idx; }
            if (s < bestMinV) { bestMinV = s; bestMinI = idx; }
            if (gy + 1 < gyE)
                s += sm->ps2[gy + 16][gx] - sm->ps2[gy][gx];
        }
    }

    sm->redMaxV[tid] = bestMaxV; sm->redMaxI[tid] = bestMaxI;
    sm->redMinV[tid] = bestMinV; sm->redMinI[tid] = bestMinI;
    __syncthreads();

    for (int st = NTHREADS / 2; st > 0; st >>= 1) {
        if (tid < st) {
            float v = sm->redMaxV[tid + st]; int i2 = sm->redMaxI[tid + st];
            if (v > sm->redMaxV[tid] ||
                (v == sm->redMaxV[tid] && i2 < sm->redMaxI[tid])) {
                sm->redMaxV[tid] = v; sm->redMaxI[tid] = i2;
            }
            float w = sm->redMinV[tid + st]; int j2 = sm->redMinI[tid + st];
            if (w < sm->redMinV[tid] ||
                (w == sm->redMinV[tid] && j2 < sm->redMinI[tid])) {
                sm->redMinV[tid] = w; sm->redMinI[tid] = j2;
            }
        }
        __syncthreads();
    }

    if (tid == 0) {
        const int imax = sm->redMaxI[0];   // class 0 top-1
        const int imin = sm->redMinI[0];   // class 1 top-1 (= argmin of S0)
        const int py0 = imax / PS, px0 = imax - py0 * PS;
        const int py1 = imin / PS, px1 = imin - py1 * PS;

        int c[8];
        c[0] = px0 * 2;                       // ox0 class0
        c[1] = min(WW - 1, px0 * 2 + 31);     // ox1
        c[2] = py0 * 2;                       // oy0
        c[3] = min(HH - 1, py0 * 2 + 31);     // oy1
        c[4] = px1 * 2;
        c[5] = min(WW - 1, px1 * 2 + 31);
        c[6] = py1 * 2;
        c[7] = min(HH - 1, py1 * 2 + 31);
        #pragma unroll
        for (int i = 0; i < 8; ++i) sm->coords[i] = c[i];

        if (oxyBase >= 0) {
            // oxy layout [B, 2, 2, 2]: [c][0] = {ox0, ox1}, [c][1] = {oy0, oy1}
            if (oxyAsInt) {
                int* o = reinterpret_cast<int*>(out) + oxyBase + (size_t)b * 8;
                #pragma unroll
                for (int i = 0; i < 8; ++i) o[i] = c[i];
            } else {
                float* o = out + oxyBase + (size_t)b * 8;
                #pragma unroll
                for (int i = 0; i < 8; ++i) o[i] = (float)c[i];
            }
        }
    }
    __syncthreads();

    // ---------------- Phase 3: mask write -----------------------------------
    if (maskBase >= 0) {
        const int ox0a = sm->coords[0], ox1a = sm->coords[1];
        const int oy0a = sm->coords[2], oy1a = sm->coords[3];
        const int ox0b = sm->coords[4], ox1b = sm->coords[5];
        const int oy0b = sm->coords[6], oy1b = sm->coords[7];

        float4* mout = reinterpret_cast<float4*>(out + maskBase + (size_t)b * HH * WW);
        #pragma unroll 4
        for (int p4 = tid; p4 < (HH * WW) / 4; p4 += NTHREADS) {
            const int y = p4 >> 6;           // 64 float4 per row
            const int x = (p4 & 63) << 2;
            const bool ya = (y >= oy0a) & (y <= oy1a);
            const bool yb = (y >= oy0b) & (y <= oy1b);
            float4 v;
            int xx;
            xx = x;     v.x = ((ya & (xx >= ox0a) & (xx <= ox1a)) |
                               (yb & (xx >= ox0b) & (xx <= ox1b))) ? 1.f : 0.f;
            xx = x + 1; v.y = ((ya & (xx >= ox0a) & (xx <= ox1a)) |
                               (yb & (xx >= ox0b) & (xx <= ox1b))) ? 1.f : 0.f;
            xx = x + 2; v.z = ((ya & (xx >= ox0a) & (xx <= ox1a)) |
                               (yb & (xx >= ox0b) & (xx <= ox1b))) ? 1.f : 0.f;
            xx = x + 3; v.w = ((ya & (xx >= ox0a) & (xx <= ox1a)) |
                               (yb & (xx >= ox0b) & (xx <= ox1b))) ? 1.f : 0.f;
            mout[p4] = v;
        }
    }
}

extern "C" void kernel_launch(void* const* d_in, const int* in_sizes, int n_in,
                              void* d_out, int out_size)
{
    const float* infeat = (const float*)d_in[0];   // [128, 2, 256, 256] f32
    // d_in[1] labelTpesudo, d_in[2] labelT, d_in[3] FeatureDA, d_in[4] k: unused

    const long long oxyN  = (long long)BATCH * 8;
    const long long maskN = (long long)BATCH * HH * WW;

    int oxyBase = -1, maskBase = -1, oxyAsInt = 0;
    const long long os = (long long)out_size;
    if (os == oxyN + maskN)      { oxyBase = 0; maskBase = (int)oxyN; }
    else if (os == maskN)        { maskBase = 0; }
    else if (os == oxyN)         { oxyBase = 0; oxyAsInt = 1; }  // sole output: int32
    else                         { oxyBase = 0; maskBase = (int)oxyN; }

    cudaFuncSetAttribute(genmask_kernel,
                         cudaFuncAttributeMaxDynamicSharedMemorySize,
                         (int)sizeof(Sm));
    genmask_kernel<<<BATCH, NTHREADS, sizeof(Sm)>>>(infeat, (float*)d_out,
                                                    oxyBase, maskBase, oxyAsInt);
}